// round 9
// baseline (speedup 1.0000x reference)
#include <cuda_runtime.h>
#include <math.h>

#define LSEQ 262144
#define NMODE 64
#define TCH 64
#define NCHUNK (LSEQ / TCH)     // 4096
#define CB 32                   // chunks per GEMM block
#define GRID_G (NCHUNK / CB)    // 128

typedef unsigned long long u64;

// Per-mode constants
__device__ float g_wre[NMODE],  g_wim[NMODE];   // w = z^TCH
__device__ float g_w4re[NMODE], g_w4im[NMODE];  // w^4
// G[m][d] = cf*z^(d+1): Gr = Re, Gin = -Im
__device__ __align__(16) float g_Gr[NMODE * TCH], g_Gin[NMODE * TCH];
// Vandermonde for partials: V[j][m] = z_m^(63-j)
__device__ __align__(16) float g_Vr[TCH * NMODE], g_Vi[TCH * NMODE];
// padded splat table: g_ktab[t] = (Ktil[t-64], Ktil[t-63]), 0 outside [0,63]
__device__ __align__(16) u64 g_ktab[128];
// intermediates [mode][chunk]
__device__ __align__(16) float2 g_P[NMODE * NCHUNK];
__device__ __align__(16) float2 g_C[NMODE * NCHUNK];

// ---- packed f32x2 helpers ----
__device__ __forceinline__ u64 pk2(float lo, float hi) {
    u64 r; asm("mov.b64 %0, {%1,%2};" : "=l"(r) : "f"(lo), "f"(hi)); return r;
}
__device__ __forceinline__ void upk2(u64 v, float& lo, float& hi) {
    asm("mov.b64 {%0,%1}, %2;" : "=f"(lo), "=f"(hi) : "l"(v));
}
__device__ __forceinline__ u64 fma2(u64 a, u64 b, u64 c) {
    u64 d; asm("fma.rn.f32x2 %0, %1, %2, %3;" : "=l"(d) : "l"(a), "l"(b), "l"(c)); return d;
}

// Float-only setup: constants, G table, V table, Ktilde pair table.
__global__ void setup_kernel(const float* __restrict__ A_re,
                             const float* __restrict__ A_im,
                             const float* __restrict__ C,
                             const float* __restrict__ log_step) {
    __shared__ float sGre[NMODE * TCH];
    __shared__ float sCfr[NMODE];
    __shared__ float sKt[TCH];
    int n = threadIdx.x;   // 64 threads
    float dt  = expf(log_step[0]);
    float ar  = A_re[n], ai = A_im[n];
    float dre = dt * ar, dim = dt * ai;
    float em  = expf(dre);
    float zr  = em * cosf(dim), zi = em * sinf(dim);
    float nr = zr - 1.f, ni = zi;
    float inv = 1.f / (ar * ar + ai * ai);
    float tre = (nr * ar + ni * ai) * inv;
    float tim = (ni * ar - nr * ai) * inv;
    float cr = C[2 * n], ci = C[2 * n + 1];
    float cfr = cr * tre - ci * tim;
    float cfi = cr * tim + ci * tre;
    // powers for w = z^64, w^4
    float p2r = zr * zr - zi * zi,          p2i = 2.f * zr * zi;
    float p4r = p2r * p2r - p2i * p2i,      p4i = 2.f * p2r * p2i;
    float p8r  = p4r * p4r - p4i * p4i,     p8i  = 2.f * p4r * p4i;
    float p16r = p8r * p8r - p8i * p8i,     p16i = 2.f * p8r * p8i;
    float p32r = p16r * p16r - p16i * p16i, p32i = 2.f * p16r * p16i;
    float wr   = p32r * p32r - p32i * p32i, wi   = 2.f * p32r * p32i;
    g_wre[n] = wr; g_wim[n] = wi;
    float w2r = wr * wr - wi * wi,     w2i = 2.f * wr * wi;
    float w4r = w2r * w2r - w2i * w2i, w4i = 2.f * w2r * w2i;
    g_w4re[n] = w4r; g_w4im[n] = w4i;
    // G table: cf*z^(d+1)
    float gr = cfr, gi = cfi;
    for (int d = 0; d < TCH; d++) {
        float t1 = gr * zr - gi * zi;
        gi = gr * zi + gi * zr; gr = t1;
        g_Gr[n * TCH + d]  = gr;
        g_Gin[n * TCH + d] = -gi;
        sGre[n * TCH + d]  = gr;
    }
    // V table: V[j][m] = z^(63-j)
    float pr = 1.f, pi = 0.f;
    for (int k = 0; k < TCH; k++) {
        g_Vr[(TCH - 1 - k) * NMODE + n] = pr;
        g_Vi[(TCH - 1 - k) * NMODE + n] = pi;
        float t1 = pr * zr - pi * zi;
        pi = pr * zi + pi * zr; pr = t1;
    }
    sCfr[n] = cfr;
    __syncthreads();
    // Ktilde[d] = sum_m Re(cf*z^d)
    float acc = 0.f;
    if (n == 0) { for (int m = 0; m < NMODE; m++) acc += sCfr[m]; }
    else        { for (int m = 0; m < NMODE; m++) acc += sGre[m * TCH + n - 1]; }
    sKt[n] = acc;
    __syncthreads();
    for (int t = n; t < 128; t += 64) {
        int li = t - 64, hi = t - 63;
        float lo = (li >= 0 && li < TCH) ? sKt[li] : 0.f;
        float hh = (hi >= 0 && hi < TCH) ? sKt[hi] : 0.f;
        g_ktab[t] = pk2(lo, hh);
    }
}

// Phase 1: chunk partials as dense GEMM  P[m][c] = sum_j V[j][m] * u[cT+j].
// Thread tile: 2 chunks x 4 modes (mode-pair packed accumulators).
__global__ __launch_bounds__(256) void pgemm_kernel(const float* __restrict__ u) {
    extern __shared__ __align__(16) char smem[];
    u64*   sU2 = (u64*)smem;            // [CB][65] splatted u
    float* sVr = (float*)(sU2 + CB * 65);  // [64][64]
    float* sVi = sVr + TCH * NMODE;
    int tid = threadIdx.x;
    int cb0 = blockIdx.x * CB;
    int ubase = cb0 * TCH;
    for (int i = tid; i < CB * TCH; i += 256) {
        float v = u[ubase + i];
        sU2[(i >> 6) * 65 + (i & 63)] = pk2(v, v);
    }
    for (int i = tid; i < TCH * NMODE; i += 256) { sVr[i] = g_Vr[i]; sVi[i] = g_Vi[i]; }
    __syncthreads();

    int cg = tid & 15, tm = tid >> 4;      // 16 chunk-groups x 16 mode-groups
    int c0 = cg * 2, m0 = tm * 4;
    u64 ar00 = 0, ar01 = 0, ar10 = 0, ar11 = 0;   // [chunk][modepair] re
    u64 ai00 = 0, ai01 = 0, ai10 = 0, ai11 = 0;   // im
    const u64* u0 = &sU2[c0 * 65];
    const u64* u1 = &sU2[(c0 + 1) * 65];
#pragma unroll 8
    for (int j = 0; j < TCH; j++) {
        u64 uj0 = u0[j], uj1 = u1[j];
        u64 vr0 = *(const u64*)&sVr[j * NMODE + m0];
        u64 vr1 = *(const u64*)&sVr[j * NMODE + m0 + 2];
        u64 vi0 = *(const u64*)&sVi[j * NMODE + m0];
        u64 vi1 = *(const u64*)&sVi[j * NMODE + m0 + 2];
        ar00 = fma2(vr0, uj0, ar00);  ar01 = fma2(vr1, uj0, ar01);
        ar10 = fma2(vr0, uj1, ar10);  ar11 = fma2(vr1, uj1, ar11);
        ai00 = fma2(vi0, uj0, ai00);  ai01 = fma2(vi1, uj0, ai01);
        ai10 = fma2(vi0, uj1, ai10);  ai11 = fma2(vi1, uj1, ai11);
    }
    int gc0 = cb0 + c0;
    float r0, r1, i0, i1;
    upk2(ar00, r0, r1); upk2(ai00, i0, i1);
    g_P[(m0 + 0) * NCHUNK + gc0] = make_float2(r0, i0);
    g_P[(m0 + 1) * NCHUNK + gc0] = make_float2(r1, i1);
    upk2(ar01, r0, r1); upk2(ai01, i0, i1);
    g_P[(m0 + 2) * NCHUNK + gc0] = make_float2(r0, i0);
    g_P[(m0 + 3) * NCHUNK + gc0] = make_float2(r1, i1);
    upk2(ar10, r0, r1); upk2(ai10, i0, i1);
    g_P[(m0 + 0) * NCHUNK + gc0 + 1] = make_float2(r0, i0);
    g_P[(m0 + 1) * NCHUNK + gc0 + 1] = make_float2(r1, i1);
    upk2(ar11, r0, r1); upk2(ai11, i0, i1);
    g_P[(m0 + 2) * NCHUNK + gc0 + 1] = make_float2(r0, i0);
    g_P[(m0 + 3) * NCHUNK + gc0 + 1] = make_float2(r1, i1);
}

// Phase 2: per-mode scan over 4096 partials; fold 4 (Horner w), scan W=w^4.
__global__ __launch_bounds__(1024) void scan_kernel() {
    __shared__ float sre[1024], sim_[1024];
    int mode = blockIdx.x, t = threadIdx.x;
    float wr = g_wre[mode], wi = g_wim[mode];
    const float2* P = &g_P[mode * NCHUNK];
    float4 pa = *(const float4*)&P[4 * t];
    float4 pb = *(const float4*)&P[4 * t + 2];
    float p0r = pa.x, p0i = pa.y, p1r = pa.z, p1i = pa.w;
    float p2r = pb.x, p2i = pb.y, p3r = pb.z, p3i = pb.w;
    float vr = p0r, vi = p0i, nr, ni;
    nr = fmaf(wr, vr, fmaf(-wi, vi, p1r));
    ni = fmaf(wi, vr, fmaf( wr, vi, p1i)); vr = nr; vi = ni;
    nr = fmaf(wr, vr, fmaf(-wi, vi, p2r));
    ni = fmaf(wi, vr, fmaf( wr, vi, p2i)); vr = nr; vi = ni;
    nr = fmaf(wr, vr, fmaf(-wi, vi, p3r));
    ni = fmaf(wi, vr, fmaf( wr, vi, p3i)); vr = nr; vi = ni;
    sre[t] = vr; sim_[t] = vi;
    float cwr = g_w4re[mode], cwi = g_w4im[mode];
    __syncthreads();
    for (int k = 1; k < 1024; k <<= 1) {
        float ore = 0.f, oim = 0.f;
        if (t >= k) { ore = sre[t - k]; oim = sim_[t - k]; }
        __syncthreads();
        vr += cwr * ore - cwi * oim;
        vi += cwr * oim + cwi * ore;
        sre[t] = vr; sim_[t] = vi;
        float nwr = cwr * cwr - cwi * cwi;
        cwi = 2.f * cwr * cwi; cwr = nwr;
        __syncthreads();
    }
    float e0r = 0.f, e0i = 0.f;
    if (t > 0) { e0r = sre[t - 1]; e0i = sim_[t - 1]; }
    float e1r = fmaf(wr, e0r, fmaf(-wi, e0i, p0r));
    float e1i = fmaf(wi, e0r, fmaf( wr, e0i, p0i));
    float e2r = fmaf(wr, e1r, fmaf(-wi, e1i, p1r));
    float e2i = fmaf(wi, e1r, fmaf( wr, e1i, p1i));
    float e3r = fmaf(wr, e2r, fmaf(-wi, e2i, p2r));
    float e3i = fmaf(wi, e2r, fmaf( wr, e2i, p2i));
    float2* Cp = &g_C[mode * NCHUNK + 4 * t];
    *(float4*)&Cp[0] = make_float4(e0r, e0i, e1r, e1i);
    *(float4*)&Cp[2] = make_float4(e2r, e2i, e3r, e3i);
}

// Phase 3: y = D*u + triangular-Toeplitz(Ktil) x u + G x carry.
// Register tile: 2 chunks x 4 deltas per thread (4 independent u64 accs).
__global__ __launch_bounds__(256) void ygemm_kernel(const float* __restrict__ u,
                                                    const float* __restrict__ D,
                                                    float* __restrict__ y) {
    extern __shared__ __align__(16) char smem[];
    u64*  sU2  = (u64*)smem;                 // [CB][65] splatted u
    u64*  sCr2 = sU2 + CB * 65;              // [64][CB] splatted carry re
    u64*  sCi2 = sCr2 + NMODE * CB;          // [64][CB] splatted carry im
    u64*  sK   = sCi2 + NMODE * CB;          // [128] padded Ktil pairs
    float* sGr  = (float*)(sK + 128);        // [64][64]
    float* sGin = sGr + NMODE * TCH;

    int tid = threadIdx.x;
    int cb0 = blockIdx.x * CB;
    int ubase = cb0 * TCH;
    for (int i = tid; i < CB * TCH; i += 256) {
        float v = u[ubase + i];
        sU2[(i >> 6) * 65 + (i & 63)] = pk2(v, v);
    }
    for (int i = tid; i < NMODE * CB; i += 256) {
        int m = i >> 5, c = i & 31;
        float2 v = g_C[m * NCHUNK + cb0 + c];
        sCr2[m * CB + c] = pk2(v.x, v.x);
        sCi2[m * CB + c] = pk2(v.y, v.y);
    }
    for (int i = tid; i < NMODE * TCH; i += 256) { sGr[i] = g_Gr[i]; sGin[i] = g_Gin[i]; }
    if (tid < 128) sK[tid] = g_ktab[tid];
    __syncthreads();

    int cg = tid & 15, dg = tid >> 4;
    int c0 = cg * 2, d0 = dg * 4;
    u64 a00 = 0, a01 = 0, a10 = 0, a11 = 0;   // [chunk][deltapair]
    const u64* u0 = &sU2[c0 * 65];
    const u64* u1 = &sU2[(c0 + 1) * 65];
    const u64* kb = &sK[64 + d0];
#pragma unroll 8
    for (int j = 0; j < TCH; j++) {
        u64 uj0 = u0[j], uj1 = u1[j];
        u64 k0 = kb[0 - j], k1 = kb[2 - j];
        a00 = fma2(k0, uj0, a00);  a01 = fma2(k1, uj0, a01);
        a10 = fma2(k0, uj1, a10);  a11 = fma2(k1, uj1, a11);
    }
#pragma unroll 8
    for (int m = 0; m < NMODE; m++) {
        u64 cr0 = sCr2[m * CB + c0], cr1 = sCr2[m * CB + c0 + 1];
        u64 ci0 = sCi2[m * CB + c0], ci1 = sCi2[m * CB + c0 + 1];
        u64 gr0 = *(const u64*)&sGr[m * TCH + d0];
        u64 gr1 = *(const u64*)&sGr[m * TCH + d0 + 2];
        u64 gi0 = *(const u64*)&sGin[m * TCH + d0];
        u64 gi1 = *(const u64*)&sGin[m * TCH + d0 + 2];
        a00 = fma2(gr0, cr0, a00);  a00 = fma2(gi0, ci0, a00);
        a01 = fma2(gr1, cr0, a01);  a01 = fma2(gi1, ci0, a01);
        a10 = fma2(gr0, cr1, a10);  a10 = fma2(gi0, ci1, a10);
        a11 = fma2(gr1, cr1, a11);  a11 = fma2(gi1, ci1, a11);
    }
    float Dv = D[0];
    int gc = cb0 + c0;
    float o0, o1, o2, o3;
    {
        float4 uv = *(const float4*)&u[gc * TCH + d0];
        upk2(a00, o0, o1); upk2(a01, o2, o3);
        float4 outv = make_float4(fmaf(Dv, uv.x, o0), fmaf(Dv, uv.y, o1),
                                  fmaf(Dv, uv.z, o2), fmaf(Dv, uv.w, o3));
        *(float4*)&y[gc * TCH + d0] = outv;
    }
    {
        float4 uv = *(const float4*)&u[(gc + 1) * TCH + d0];
        upk2(a10, o0, o1); upk2(a11, o2, o3);
        float4 outv = make_float4(fmaf(Dv, uv.x, o0), fmaf(Dv, uv.y, o1),
                                  fmaf(Dv, uv.z, o2), fmaf(Dv, uv.w, o3));
        *(float4*)&y[(gc + 1) * TCH + d0] = outv;
    }
}

#define PG_SMEM (CB * 65 * 8 + TCH * NMODE * 4 * 2)
#define YG_SMEM (CB * 65 * 8 + NMODE * CB * 8 * 2 + 128 * 8 + NMODE * TCH * 4 * 2)

extern "C" void kernel_launch(void* const* d_in, const int* in_sizes, int n_in,
                              void* d_out, int out_size) {
    const float* u        = (const float*)d_in[0];
    const float* A_re     = (const float*)d_in[1];
    const float* A_im     = (const float*)d_in[2];
    const float* C        = (const float*)d_in[3];
    const float* D        = (const float*)d_in[4];
    const float* log_step = (const float*)d_in[5];
    float* y = (float*)d_out;

    cudaFuncSetAttribute(pgemm_kernel,
                         cudaFuncAttributeMaxDynamicSharedMemorySize, PG_SMEM);
    cudaFuncSetAttribute(ygemm_kernel,
                         cudaFuncAttributeMaxDynamicSharedMemorySize, YG_SMEM);

    setup_kernel<<<1, NMODE>>>(A_re, A_im, C, log_step);
    pgemm_kernel<<<GRID_G, 256, PG_SMEM>>>(u);
    scan_kernel<<<NMODE, 1024>>>();
    ygemm_kernel<<<GRID_G, 256, YG_SMEM>>>(u, D, y);
}

// round 10
// speedup vs baseline: 1.0429x; 1.0429x over previous
#include <cuda_runtime.h>
#include <math.h>

#define LSEQ 262144
#define NMODE 64
#define TCH 64
#define NCHUNK (LSEQ / TCH)     // 4096
#define CB 16                   // chunks per GEMM block
#define GRID_G (NCHUNK / CB)    // 256

typedef unsigned long long u64;

// Per-mode scan constants
__device__ float g_wre[NMODE],  g_wim[NMODE];   // w = z^TCH
__device__ float g_w4re[NMODE], g_w4im[NMODE];  // w^4
// Packed tables (float4 for single coalesced LDG.128):
// g_Vpk[j][mp] = (Vr[2mp], Vr[2mp+1], Vi[2mp], Vi[2mp+1]),  V[j][m] = z_m^(63-j)
__device__ __align__(16) float4 g_Vpk[TCH * 32];
// g_Gpk[m][dp] = (Gr[m][2dp], Gr[m][2dp+1], Gin[m][2dp], Gin[m][2dp+1]),
//   G[m][d] = cf_m * z_m^(d+1), Gin = -Im(G)
__device__ __align__(16) float4 g_Gpk[NMODE * 32];
// padded pair table: g_ktab[t] = (Ktil[t-64], Ktil[t-63]), 0 outside [0,63]
__device__ __align__(16) u64 g_ktab[128];
// intermediates [mode][chunk]
__device__ __align__(16) float2 g_P[NMODE * NCHUNK];
__device__ __align__(16) float2 g_C[NMODE * NCHUNK];

// ---- packed f32x2 helpers ----
__device__ __forceinline__ u64 pk2(float lo, float hi) {
    u64 r; asm("mov.b64 %0, {%1,%2};" : "=l"(r) : "f"(lo), "f"(hi)); return r;
}
__device__ __forceinline__ void upk2(u64 v, float& lo, float& hi) {
    asm("mov.b64 {%0,%1}, %2;" : "=f"(lo), "=f"(hi) : "l"(v));
}
__device__ __forceinline__ u64 fma2(u64 a, u64 b, u64 c) {
    u64 d; asm("fma.rn.f32x2 %0, %1, %2, %3;" : "=l"(d) : "l"(a), "l"(b), "l"(c)); return d;
}

// Float-only setup: scan constants + packed V/G tables + Ktilde pair table.
__global__ void setup_kernel(const float* __restrict__ A_re,
                             const float* __restrict__ A_im,
                             const float* __restrict__ C,
                             const float* __restrict__ log_step) {
    __shared__ float sRe[NMODE * 65], sIm[NMODE * 65];   // pitch 65: conflict-free
    __shared__ float sCfr[NMODE], sKt[TCH];
    int n = threadIdx.x;   // 64 threads = one mode each
    float dt  = expf(log_step[0]);
    float ar  = A_re[n], ai = A_im[n];
    float dre = dt * ar, dim = dt * ai;
    float em  = expf(dre);
    float zr  = em * cosf(dim), zi = em * sinf(dim);
    float nr = zr - 1.f, ni = zi;
    float inv = 1.f / (ar * ar + ai * ai);
    float tre = (nr * ar + ni * ai) * inv;
    float tim = (ni * ar - nr * ai) * inv;
    float cr = C[2 * n], ci = C[2 * n + 1];
    float cfr = cr * tre - ci * tim;
    float cfi = cr * tim + ci * tre;
    // w = z^64, w^4
    float p2r = zr * zr - zi * zi,          p2i = 2.f * zr * zi;
    float p4r = p2r * p2r - p2i * p2i,      p4i = 2.f * p2r * p2i;
    float p8r  = p4r * p4r - p4i * p4i,     p8i  = 2.f * p4r * p4i;
    float p16r = p8r * p8r - p8i * p8i,     p16i = 2.f * p8r * p8i;
    float p32r = p16r * p16r - p16i * p16i, p32i = 2.f * p16r * p16i;
    float wr   = p32r * p32r - p32i * p32i, wi   = 2.f * p32r * p32i;
    g_wre[n] = wr; g_wim[n] = wi;
    float w2r = wr * wr - wi * wi,     w2i = 2.f * wr * wi;
    g_w4re[n] = w2r * w2r - w2i * w2i;
    g_w4im[n] = 2.f * w2r * w2i;
    sCfr[n] = cfr;
    // --- V staging: sRe[j*65+n] = Re z^(63-j) ---
    {
        float pr = 1.f, pi = 0.f;
        for (int k = 0; k < TCH; k++) {
            int j = TCH - 1 - k;
            sRe[j * 65 + n] = pr;  sIm[j * 65 + n] = pi;
            float t1 = pr * zr - pi * zi;
            pi = pr * zi + pi * zr; pr = t1;
        }
    }
    __syncthreads();
    // pack V row j = n
    for (int mp = 0; mp < 32; mp++) {
        g_Vpk[n * 32 + mp] = make_float4(sRe[n * 65 + 2 * mp], sRe[n * 65 + 2 * mp + 1],
                                         sIm[n * 65 + 2 * mp], sIm[n * 65 + 2 * mp + 1]);
    }
    __syncthreads();
    // --- G staging: sRe[n*65+d] = Re(cf*z^(d+1)), sIm = Im ---
    {
        float gr = cfr, gi = cfi;
        for (int d = 0; d < TCH; d++) {
            float t1 = gr * zr - gi * zi;
            gi = gr * zi + gi * zr; gr = t1;
            sRe[n * 65 + d] = gr;  sIm[n * 65 + d] = gi;
        }
    }
    __syncthreads();
    // pack G row m = n (Gin = -Im)
    for (int dp = 0; dp < 32; dp++) {
        g_Gpk[n * 32 + dp] = make_float4(sRe[n * 65 + 2 * dp], sRe[n * 65 + 2 * dp + 1],
                                         -sIm[n * 65 + 2 * dp], -sIm[n * 65 + 2 * dp + 1]);
    }
    // Ktilde[d]: d=0 -> sum_m cfr; d>0 -> sum_m Gr[m][d-1]
    {
        float acc = 0.f;
        if (n == 0) { for (int m = 0; m < NMODE; m++) acc += sCfr[m]; }
        else        { for (int m = 0; m < NMODE; m++) acc += sRe[m * 65 + n - 1]; }
        sKt[n] = acc;
    }
    __syncthreads();
    for (int t = n; t < 128; t += 64) {
        int li = t - 64, hi = t - 63;
        float lo = (li >= 0 && li < TCH) ? sKt[li] : 0.f;
        float hh = (hi >= 0 && hi < TCH) ? sKt[hi] : 0.f;
        g_ktab[t] = pk2(lo, hh);
    }
}

// Phase 1: partials as GEMM  P[m][c] = sum_j V[j][m]*u[cT+j].
// Warp = 2 chunks x 32 mode-pairs (mp = lane). u broadcast, V coalesced LDG.128.
__global__ __launch_bounds__(256) void pgemm_kernel(const float* __restrict__ u) {
    __shared__ __align__(16) u64 sU2[CB * 65];            // splatted u
    __shared__ __align__(16) float2 sPst[NMODE * 17];     // staging, pitch 17
    int tid = threadIdx.x;
    int cb0 = blockIdx.x * CB;
    for (int i = tid; i < CB * TCH; i += 256) {
        float v = u[cb0 * TCH + i];
        sU2[(i >> 6) * 65 + (i & 63)] = pk2(v, v);
    }
    __syncthreads();

    int lane = tid & 31, c0 = (tid >> 5) * 2;
    u64 ar0 = 0, ai0 = 0, ar1 = 0, ai1 = 0;
    const u64* u0 = &sU2[c0 * 65];
    const u64* u1 = &sU2[(c0 + 1) * 65];
#pragma unroll 8
    for (int j = 0; j < TCH; j++) {
        float4 v4 = __ldg(&g_Vpk[j * 32 + lane]);
        u64 vr = pk2(v4.x, v4.y), vi = pk2(v4.z, v4.w);
        u64 uj0 = u0[j], uj1 = u1[j];
        ar0 = fma2(vr, uj0, ar0);  ai0 = fma2(vi, uj0, ai0);
        ar1 = fma2(vr, uj1, ar1);  ai1 = fma2(vi, uj1, ai1);
    }
    float r0, r1, i0, i1;
    upk2(ar0, r0, r1); upk2(ai0, i0, i1);
    sPst[(2 * lane) * 17 + c0]     = make_float2(r0, i0);
    sPst[(2 * lane + 1) * 17 + c0] = make_float2(r1, i1);
    upk2(ar1, r0, r1); upk2(ai1, i0, i1);
    sPst[(2 * lane) * 17 + c0 + 1]     = make_float2(r0, i0);
    sPst[(2 * lane + 1) * 17 + c0 + 1] = make_float2(r1, i1);
    __syncthreads();
    // coalesced writeout: 64 rows x 16 float2
    int row = tid >> 2, cq = (tid & 3) * 4;
    float2 a = sPst[row * 17 + cq],     b = sPst[row * 17 + cq + 1];
    float2 c = sPst[row * 17 + cq + 2], d = sPst[row * 17 + cq + 3];
    float2* gp = &g_P[row * NCHUNK + cb0 + cq];
    *(float4*)&gp[0] = make_float4(a.x, a.y, b.x, b.y);
    *(float4*)&gp[2] = make_float4(c.x, c.y, d.x, d.y);
}

// Phase 2: per-mode scan over 4096 partials; fold 4 (Horner w), scan W=w^4.
__global__ __launch_bounds__(1024) void scan_kernel() {
    __shared__ float sre[1024], sim_[1024];
    int mode = blockIdx.x, t = threadIdx.x;
    float wr = g_wre[mode], wi = g_wim[mode];
    const float2* P = &g_P[mode * NCHUNK];
    float4 pa = *(const float4*)&P[4 * t];
    float4 pb = *(const float4*)&P[4 * t + 2];
    float p0r = pa.x, p0i = pa.y, p1r = pa.z, p1i = pa.w;
    float p2r = pb.x, p2i = pb.y, p3r = pb.z, p3i = pb.w;
    float vr = p0r, vi = p0i, nr, ni;
    nr = fmaf(wr, vr, fmaf(-wi, vi, p1r));
    ni = fmaf(wi, vr, fmaf( wr, vi, p1i)); vr = nr; vi = ni;
    nr = fmaf(wr, vr, fmaf(-wi, vi, p2r));
    ni = fmaf(wi, vr, fmaf( wr, vi, p2i)); vr = nr; vi = ni;
    nr = fmaf(wr, vr, fmaf(-wi, vi, p3r));
    ni = fmaf(wi, vr, fmaf( wr, vi, p3i)); vr = nr; vi = ni;
    sre[t] = vr; sim_[t] = vi;
    float cwr = g_w4re[mode], cwi = g_w4im[mode];
    __syncthreads();
    for (int k = 1; k < 1024; k <<= 1) {
        float ore = 0.f, oim = 0.f;
        if (t >= k) { ore = sre[t - k]; oim = sim_[t - k]; }
        __syncthreads();
        vr += cwr * ore - cwi * oim;
        vi += cwr * oim + cwi * ore;
        sre[t] = vr; sim_[t] = vi;
        float nwr = cwr * cwr - cwi * cwi;
        cwi = 2.f * cwr * cwi; cwr = nwr;
        __syncthreads();
    }
    float e0r = 0.f, e0i = 0.f;
    if (t > 0) { e0r = sre[t - 1]; e0i = sim_[t - 1]; }
    float e1r = fmaf(wr, e0r, fmaf(-wi, e0i, p0r));
    float e1i = fmaf(wi, e0r, fmaf( wr, e0i, p0i));
    float e2r = fmaf(wr, e1r, fmaf(-wi, e1i, p1r));
    float e2i = fmaf(wi, e1r, fmaf( wr, e1i, p1i));
    float e3r = fmaf(wr, e2r, fmaf(-wi, e2i, p2r));
    float e3i = fmaf(wi, e2r, fmaf( wr, e2i, p2i));
    float2* Cp = &g_C[mode * NCHUNK + 4 * t];
    *(float4*)&Cp[0] = make_float4(e0r, e0i, e1r, e1i);
    *(float4*)&Cp[2] = make_float4(e2r, e2i, e3r, e3i);
}

// Phase 3: y = D*u + triangular-Toeplitz(Ktil) x u + G x carry.
// Warp = 2 chunks x 32 delta-pairs (dp = lane). u/C/K broadcast, G coalesced LDG.128.
__global__ __launch_bounds__(256) void ygemm_kernel(const float* __restrict__ u,
                                                    const float* __restrict__ D,
                                                    float* __restrict__ y) {
    __shared__ __align__(16) u64 sU2[CB * 65];        // splatted u
    __shared__ __align__(16) float2 sC[NMODE * CB];   // carries
    __shared__ __align__(16) u64 sK[128];             // Ktil pairs
    int tid = threadIdx.x;
    int cb0 = blockIdx.x * CB;
    for (int i = tid; i < CB * TCH; i += 256) {
        float v = u[cb0 * TCH + i];
        sU2[(i >> 6) * 65 + (i & 63)] = pk2(v, v);
    }
    for (int i = tid; i < NMODE * CB; i += 256) {
        int m = i >> 4, c = i & 15;
        sC[m * CB + c] = g_C[m * NCHUNK + cb0 + c];
    }
    if (tid < 128) sK[tid] = g_ktab[tid];
    __syncthreads();

    int lane = tid & 31, c0 = (tid >> 5) * 2;
    int d0 = 2 * lane;
    u64 a0 = 0, a1 = 0;   // (chunk c0 | c0+1), deltas (d0, d0+1)
    const u64* u0 = &sU2[c0 * 65];
    const u64* u1 = &sU2[(c0 + 1) * 65];
    const u64* kb = &sK[64 + d0];
#pragma unroll 8
    for (int j = 0; j < TCH; j++) {
        u64 kk = kb[-j];
        a0 = fma2(kk, u0[j], a0);
        a1 = fma2(kk, u1[j], a1);
    }
#pragma unroll 8
    for (int m = 0; m < NMODE; m++) {
        float4 g4 = __ldg(&g_Gpk[m * 32 + lane]);
        u64 gr = pk2(g4.x, g4.y), gi = pk2(g4.z, g4.w);
        float2 cA = sC[m * CB + c0];
        float2 cB = sC[m * CB + c0 + 1];
        a0 = fma2(gr, pk2(cA.x, cA.x), a0);
        a0 = fma2(gi, pk2(cA.y, cA.y), a0);
        a1 = fma2(gr, pk2(cB.x, cB.x), a1);
        a1 = fma2(gi, pk2(cB.y, cB.y), a1);
    }
    float Dv = D[0];
    float o0, o1;
    {
        int idx = (cb0 + c0) * TCH + d0;
        float2 uv = *(const float2*)&u[idx];
        upk2(a0, o0, o1);
        *(float2*)&y[idx] = make_float2(fmaf(Dv, uv.x, o0), fmaf(Dv, uv.y, o1));
    }
    {
        int idx = (cb0 + c0 + 1) * TCH + d0;
        float2 uv = *(const float2*)&u[idx];
        upk2(a1, o0, o1);
        *(float2*)&y[idx] = make_float2(fmaf(Dv, uv.x, o0), fmaf(Dv, uv.y, o1));
    }
}

extern "C" void kernel_launch(void* const* d_in, const int* in_sizes, int n_in,
                              void* d_out, int out_size) {
    const float* u        = (const float*)d_in[0];
    const float* A_re     = (const float*)d_in[1];
    const float* A_im     = (const float*)d_in[2];
    const float* C        = (const float*)d_in[3];
    const float* D        = (const float*)d_in[4];
    const float* log_step = (const float*)d_in[5];
    float* y = (float*)d_out;

    setup_kernel<<<1, NMODE>>>(A_re, A_im, C, log_step);
    pgemm_kernel<<<GRID_G, 256>>>(u);
    scan_kernel<<<NMODE, 1024>>>();
    ygemm_kernel<<<GRID_G, 256>>>(u, D, y);
}